// round 11
// baseline (speedup 1.0000x reference)
#include <cuda_runtime.h>

// Shapes fixed by reference setup_inputs()
#define BB      16
#define NPTS    1024          // H*W
#define DD      128           // = 32 float4 chunks
#define KK      32
#define GPB     16            // chunks (CTAs) per batch
#define PPB     (NPTS / GPB)  // 64 points per CTA
#define NTHREADS 512          // 16 warps
#define NCHUNK  (BB * GPB)    // 256

// Shared layout: xs[64][33] f4 | cs[32][34] f4 | Ad[64][17] f4 (dup pairs) | x2s[64] f
#define XS_STRIDE 33
#define CS_STRIDE 34
#define AD_STRIDE 17          // float4 units per point-row: 16 used (32 k dup'd) + 1 pad
#define XS_BYTES  (PPB * XS_STRIDE * 16)            // 33792
#define CS_BYTES  (KK * CS_STRIDE * 16)             // 17408
#define AD_BYTES  (PPB * AD_STRIDE * 16)            // 17408
#define SMEM_BYTES (XS_BYTES + CS_BYTES + AD_BYTES + PPB * 4)  // 68864

__device__ __forceinline__ unsigned long long ffma2_(unsigned long long a,
                                                     unsigned long long b,
                                                     unsigned long long c) {
    unsigned long long d;
    asm("fma.rn.f32x2 %0, %1, %2, %3;" : "=l"(d) : "l"(a), "l"(b), "l"(c));
    return d;
}
__device__ __forceinline__ float2 unpack2(unsigned long long v) {
    float2 r;
    asm("mov.b64 {%0, %1}, %2;" : "=f"(r.x), "=f"(r.y) : "l"(v));
    return r;
}
// Vector reduction: fire-and-forget float4 add to global (sm_90+)
__device__ __forceinline__ void red_add_v4(float* p, float a, float b, float c, float d) {
    asm volatile("red.global.add.v4.f32 [%0], {%1, %2, %3, %4};"
                 :: "l"(p), "f"(a), "f"(b), "f"(c), "f"(d) : "memory");
}

__global__ void ev_zero_kernel(float4* __restrict__ out) {
    out[blockIdx.x * 256 + threadIdx.x] = make_float4(0.f, 0.f, 0.f, 0.f);
}

__global__ __launch_bounds__(NTHREADS, 2)
void ev_encode_kernel(const float* __restrict__ x,
                      const float* __restrict__ cw,
                      const float* __restrict__ scale,
                      float* __restrict__ out) {
    extern __shared__ char sraw[];
    float4* xs  = (float4*)sraw;                          // [PPB][33]
    float4* cs  = (float4*)(sraw + XS_BYTES);             // [KK][34] rotated
    float4* Ad4 = (float4*)(sraw + XS_BYTES + CS_BYTES);  // [PPB][17]: (a,a) dup pairs
    float*  x2s = (float*)(sraw + XS_BYTES + CS_BYTES + AD_BYTES);  // [PPB]

    const int t    = threadIdx.x;
    const int lane = t & 31;
    const int w    = t >> 5;              // 0..15
    const int b    = blockIdx.x >> 4;
    const int g    = blockIdx.x & 15;
    const int mi   = lane & 1;            // point-subgroup (2 x 2 pts)
    const int ni   = lane >> 1;           // k-pair index (16 pairs)

    // ---- Phase A1: stage x tile; warp w loads complete rows w, w+16, w+32, w+48;
    //      chunk = lane -> fold ||x||^2 reduction into the staging pass ----
    const float4* xg = (const float4*)(x + ((size_t)b * NPTS + (size_t)g * PPB) * DD);
    #pragma unroll
    for (int i = 0; i < 4; ++i) {
        int p = w + 16 * i;
        float4 v = xg[p * 32 + lane];
        xs[p * XS_STRIDE + lane] = v;
        float s2 = v.x * v.x + v.y * v.y + v.z * v.z + v.w * v.w;
        #pragma unroll
        for (int o = 16; o; o >>= 1) s2 += __shfl_xor_sync(0xffffffffu, s2, o);
        if (lane == 0) x2s[p] = s2;
    }

    // ---- Phase A2: augmented codewords w_k = -2*s_k*c_k at slot (d4 + k/2)&31;
    //      slot 32 = (s_k, s_k*||c_k||^2, 0, 0). Warp w builds rows 2w, 2w+1. ----
    #pragma unroll
    for (int j = 0; j < 2; ++j) {
        int k = w * 2 + j;
        float4 c = ((const float4*)cw)[k * 32 + lane];
        float s  = scale[k];
        float c2 = c.x * c.x + c.y * c.y + c.z * c.z + c.w * c.w;
        #pragma unroll
        for (int o = 16; o; o >>= 1) c2 += __shfl_xor_sync(0xffffffffu, c2, o);
        float m2 = -2.f * s;
        cs[k * CS_STRIDE + ((lane + (k >> 1)) & 31)] =
            make_float4(m2 * c.x, m2 * c.y, m2 * c.z, m2 * c.w);
        if (lane == 0)
            cs[k * CS_STRIDE + 32] = make_float4(s, s * c2, 0.f, 0.f);
    }
    __syncthreads();

    // ---- Phase C: stage-1 GEMM (logits), 2 pts x 2 k per lane ----
    unsigned long long acc[2][2];
    acc[0][0] = 0ull; acc[0][1] = 0ull; acc[1][0] = 0ull; acc[1][1] = 0ull;

    const int pbase = w * 4 + mi * 2;
    const ulonglong2* xs2 = (const ulonglong2*)xs;
    const ulonglong2* csrow0 = (const ulonglong2*)cs + (2 * ni + 0) * CS_STRIDE;
    const ulonglong2* csrow1 = (const ulonglong2*)cs + (2 * ni + 1) * CS_STRIDE;

    #pragma unroll 8
    for (int d4 = 0; d4 < 32; ++d4) {
        int cslot = (d4 + ni) & 31;
        ulonglong2 cv0 = csrow0[cslot];
        ulonglong2 cv1 = csrow1[cslot];
        #pragma unroll
        for (int p = 0; p < 2; ++p) {
            ulonglong2 xv = xs2[(pbase + p) * XS_STRIDE + d4];   // linear in d4
            acc[p][0] = ffma2_(cv0.x, xv.x, acc[p][0]);
            acc[p][0] = ffma2_(cv0.y, xv.y, acc[p][0]);
            acc[p][1] = ffma2_(cv1.x, xv.x, acc[p][1]);
            acc[p][1] = ffma2_(cv1.y, xv.y, acc[p][1]);
        }
    }

    float4 cc0 = cs[(2 * ni + 0) * CS_STRIDE + 32];   // (s, s*c2, 0, 0)
    float4 cc1 = cs[(2 * ni + 1) * CS_STRIDE + 32];

    // ---- softmax over K=32 (butterfly on ni bits; mi bit untouched) ----
    //      store A pre-duplicated: Ad[pt][ni] = (a_{2ni}, a_{2ni}, a_{2ni+1}, a_{2ni+1})
    #pragma unroll
    for (int p = 0; p < 2; ++p) {
        float x2 = x2s[pbase + p];                     // broadcast LDS
        float2 u0 = unpack2(acc[p][0]);
        float2 u1 = unpack2(acc[p][1]);
        float SL0 = (u0.x + u0.y) + fmaf(cc0.x, x2, cc0.y);
        float SL1 = (u1.x + u1.y) + fmaf(cc1.x, x2, cc1.y);
        float m = fmaxf(SL0, SL1);
        #pragma unroll
        for (int o = 2; o <= 16; o <<= 1) m = fmaxf(m, __shfl_xor_sync(0xffffffffu, m, o));
        float e0 = __expf(SL0 - m);
        float e1 = __expf(SL1 - m);
        float ssum = e0 + e1;
        #pragma unroll
        for (int o = 2; o <= 16; o <<= 1) ssum += __shfl_xor_sync(0xffffffffu, ssum, o);
        float inv = 1.f / ssum;
        float a0 = e0 * inv, a1 = e1 * inv;
        Ad4[(pbase + p) * AD_STRIDE + ni] = make_float4(a0, a0, a1, a1);  // 1 STS.128
    }
    __syncthreads();

    // ---- Phase D: E[k][d] = sum_p A[p][k]*x[p][d] ----
    //      warp w owns k pair {2w, 2w+1}; lane owns d-chunk d4=lane (4 d).
    //      Per point: 1 distinct LDS.128 (x slice) + 1 broadcast LDS.128 (A dup pair).
    unsigned long long acc2[4];
    acc2[0] = 0ull; acc2[1] = 0ull; acc2[2] = 0ull; acc2[3] = 0ull;
    const ulonglong2* Ad2 = (const ulonglong2*)Ad4;

    #pragma unroll 8
    for (int p = 0; p < PPB; ++p) {
        ulonglong2 xv = xs2[p * XS_STRIDE + lane];       // distinct, conflict-free
        ulonglong2 a  = Ad2[p * AD_STRIDE + w];          // (a0,a0),(a1,a1)  bcast
        acc2[0] = ffma2_(a.x, xv.x, acc2[0]);
        acc2[1] = ffma2_(a.x, xv.y, acc2[1]);
        acc2[2] = ffma2_(a.y, xv.x, acc2[2]);
        acc2[3] = ffma2_(a.y, xv.y, acc2[3]);
    }

    // ---- sA_j = sum_p A[p][2w+j]: lane-parallel partials + warp butterfly ----
    float2 sa = make_float2(0.f, 0.f);
    #pragma unroll
    for (int h = 0; h < 2; ++h) {
        int p = lane + 32 * h;
        float4 u = Ad4[p * AD_STRIDE + w];           // a0,a0,a1,a1
        sa.x += u.x; sa.y += u.z;
    }
    #pragma unroll
    for (int o = 16; o; o >>= 1) {
        sa.x += __shfl_xor_sync(0xffffffffu, sa.x, o);
        sa.y += __shfl_xor_sync(0xffffffffu, sa.y, o);
    }

    // ---- epilogue: out[b][2w+j][4*lane..+3] += acc - sA_j * c  (red.v4) ----
    const float sa_arr[2] = {sa.x, sa.y};
    #pragma unroll
    for (int j = 0; j < 2; ++j) {
        int k = 2 * w + j;
        float4 c = ((const float4*)cw)[k * 32 + lane];     // coalesced LDG.128
        float2 lo = unpack2(acc2[2 * j + 0]);
        float2 hi = unpack2(acc2[2 * j + 1]);
        float sj = sa_arr[j];
        red_add_v4(out + ((size_t)b * KK + k) * DD + 4 * lane,
                   fmaf(-sj, c.x, lo.x),
                   fmaf(-sj, c.y, lo.y),
                   fmaf(-sj, c.z, hi.x),
                   fmaf(-sj, c.w, hi.y));
    }
}

extern "C" void kernel_launch(void* const* d_in, const int* in_sizes, int n_in,
                              void* d_out, int out_size) {
    const float* x  = (const float*)d_in[0];   // [16,32,32,128]
    const float* cw = (const float*)d_in[1];   // [32,128]
    const float* sc = (const float*)d_in[2];   // [32]
    float* out = (float*)d_out;                // [16,32,128]

    cudaFuncSetAttribute(ev_encode_kernel,
                         cudaFuncAttributeMaxDynamicSharedMemorySize, SMEM_BYTES);

    // out is poisoned by the harness; REDs need zeros
    ev_zero_kernel<<<(BB * KK * DD / 4) / 256, 256>>>((float4*)out);
    ev_encode_kernel<<<NCHUNK, NTHREADS, SMEM_BYTES>>>(x, cw, sc, out);
}

// round 12
// speedup vs baseline: 1.2059x; 1.2059x over previous
#include <cuda_runtime.h>

// Shapes fixed by reference setup_inputs()
#define BB      16
#define NPTS    1024          // H*W
#define DD      128           // = 32 float4 chunks
#define KK      32
#define GPB     16            // chunks (CTAs) per batch
#define PPB     (NPTS / GPB)  // 64 points per CTA
#define NTHREADS 256
#define NCHUNK  (BB * GPB)    // 256

// Shared layout: xs[64][33] f4 | cs[32][34] f4 (later reused as merge buf) |
//                Ad[64][17] f4 (dup pairs) | x2s[64] f
#define XS_STRIDE 33
#define CS_STRIDE 34
#define AD_STRIDE 17
#define XS_BYTES  (PPB * XS_STRIDE * 16)            // 33792
#define CS_BYTES  (KK * CS_STRIDE * 16)             // 17408
#define AD_BYTES  (PPB * AD_STRIDE * 16)            // 17408
#define SMEM_BYTES (XS_BYTES + CS_BYTES + AD_BYTES + PPB * 4)  // 68864

__device__ __forceinline__ unsigned long long ffma2_(unsigned long long a,
                                                     unsigned long long b,
                                                     unsigned long long c) {
    unsigned long long d;
    asm("fma.rn.f32x2 %0, %1, %2, %3;" : "=l"(d) : "l"(a), "l"(b), "l"(c));
    return d;
}
__device__ __forceinline__ unsigned long long add2_(unsigned long long a,
                                                    unsigned long long b) {
    unsigned long long d;
    asm("add.rn.f32x2 %0, %1, %2;" : "=l"(d) : "l"(a), "l"(b));
    return d;
}
__device__ __forceinline__ float2 unpack2(unsigned long long v) {
    float2 r;
    asm("mov.b64 {%0, %1}, %2;" : "=f"(r.x), "=f"(r.y) : "l"(v));
    return r;
}
// Vector reduction: fire-and-forget float4 add to global (sm_90+)
__device__ __forceinline__ void red_add_v4(float* p, float a, float b, float c, float d) {
    asm volatile("red.global.add.v4.f32 [%0], {%1, %2, %3, %4};"
                 :: "l"(p), "f"(a), "f"(b), "f"(c), "f"(d) : "memory");
}

__global__ void ev_zero_kernel(float4* __restrict__ out) {
    out[blockIdx.x * 256 + threadIdx.x] = make_float4(0.f, 0.f, 0.f, 0.f);
}

__global__ __launch_bounds__(NTHREADS, 2)
void ev_encode_kernel(const float* __restrict__ x,
                      const float* __restrict__ cw,
                      const float* __restrict__ scale,
                      float* __restrict__ out) {
    extern __shared__ char sraw[];
    float4* xs  = (float4*)sraw;                          // [PPB][33]
    float4* cs  = (float4*)(sraw + XS_BYTES);             // [KK][34] rotated
    float4* Ad4 = (float4*)(sraw + XS_BYTES + CS_BYTES);  // [PPB][17]: (a,a) dup pairs
    float*  x2s = (float*)(sraw + XS_BYTES + CS_BYTES + AD_BYTES);  // [PPB]
    // Phase-D merge buffers reuse the cs region (dead after softmax):
    ulonglong2* buf2 = (ulonglong2*)cs;                   // [4v][8jj][32 lane] 16B = 16KB
    float*      sabf = (float*)(sraw + XS_BYTES + 16384); // [4v][8kk] floats (128B)

    const int t    = threadIdx.x;
    const int lane = t & 31;
    const int w    = t >> 5;              // 0..7
    const int b    = blockIdx.x >> 4;
    const int g    = blockIdx.x & 15;
    const int mi   = lane & 1;            // point-subgroup (2 x 4 pts)
    const int ni   = lane >> 1;           // k-pair index (16 pairs)

    // ---- Phase A1: stage x tile; warp w loads complete rows w, w+8, ...
    const float4* xg = (const float4*)(x + ((size_t)b * NPTS + (size_t)g * PPB) * DD);
    #pragma unroll
    for (int i = 0; i < 8; ++i) {
        int p = w + 8 * i;
        float4 v = xg[p * 32 + lane];
        xs[p * XS_STRIDE + lane] = v;
        float s2 = v.x * v.x + v.y * v.y + v.z * v.z + v.w * v.w;
        #pragma unroll
        for (int o = 16; o; o >>= 1) s2 += __shfl_xor_sync(0xffffffffu, s2, o);
        if (lane == 0) x2s[p] = s2;
    }

    // ---- Phase A2: augmented codewords w_k = -2*s_k*c_k at slot (d4 + k/2)&31;
    //      slot 32 = (s_k, s_k*||c_k||^2, 0, 0). Warp w builds rows 4w..4w+3. ----
    #pragma unroll
    for (int j = 0; j < 4; ++j) {
        int k = w * 4 + j;
        float4 c = ((const float4*)cw)[k * 32 + lane];
        float s  = scale[k];
        float c2 = c.x * c.x + c.y * c.y + c.z * c.z + c.w * c.w;
        #pragma unroll
        for (int o = 16; o; o >>= 1) c2 += __shfl_xor_sync(0xffffffffu, c2, o);
        float m2 = -2.f * s;
        cs[k * CS_STRIDE + ((lane + (k >> 1)) & 31)] =
            make_float4(m2 * c.x, m2 * c.y, m2 * c.z, m2 * c.w);
        if (lane == 0)
            cs[k * CS_STRIDE + 32] = make_float4(s, s * c2, 0.f, 0.f);
    }
    __syncthreads();

    // ---- Phase C: stage-1 GEMM (logits), 4 pts x 2 k per lane ----
    unsigned long long acc[4][2];
    #pragma unroll
    for (int p = 0; p < 4; ++p) { acc[p][0] = 0ull; acc[p][1] = 0ull; }

    const int pbase = w * 8 + mi * 4;
    const ulonglong2* xs2 = (const ulonglong2*)xs;
    const ulonglong2* csrow0 = (const ulonglong2*)cs + (2 * ni + 0) * CS_STRIDE;
    const ulonglong2* csrow1 = (const ulonglong2*)cs + (2 * ni + 1) * CS_STRIDE;

    #pragma unroll 8
    for (int d4 = 0; d4 < 32; ++d4) {
        int cslot = (d4 + ni) & 31;
        ulonglong2 cv0 = csrow0[cslot];
        ulonglong2 cv1 = csrow1[cslot];
        #pragma unroll
        for (int p = 0; p < 4; ++p) {
            ulonglong2 xv = xs2[(pbase + p) * XS_STRIDE + d4];
            acc[p][0] = ffma2_(cv0.x, xv.x, acc[p][0]);
            acc[p][0] = ffma2_(cv0.y, xv.y, acc[p][0]);
            acc[p][1] = ffma2_(cv1.x, xv.x, acc[p][1]);
            acc[p][1] = ffma2_(cv1.y, xv.y, acc[p][1]);
        }
    }

    float4 cc0 = cs[(2 * ni + 0) * CS_STRIDE + 32];   // (s, s*c2, 0, 0)
    float4 cc1 = cs[(2 * ni + 1) * CS_STRIDE + 32];

    // ---- softmax over K=32; store A pre-duplicated pairs ----
    #pragma unroll
    for (int p = 0; p < 4; ++p) {
        float x2 = x2s[pbase + p];
        float2 u0 = unpack2(acc[p][0]);
        float2 u1 = unpack2(acc[p][1]);
        float SL0 = (u0.x + u0.y) + fmaf(cc0.x, x2, cc0.y);
        float SL1 = (u1.x + u1.y) + fmaf(cc1.x, x2, cc1.y);
        float m = fmaxf(SL0, SL1);
        #pragma unroll
        for (int o = 2; o <= 16; o <<= 1) m = fmaxf(m, __shfl_xor_sync(0xffffffffu, m, o));
        float e0 = __expf(SL0 - m);
        float e1 = __expf(SL1 - m);
        float ssum = e0 + e1;
        #pragma unroll
        for (int o = 2; o <= 16; o <<= 1) ssum += __shfl_xor_sync(0xffffffffu, ssum, o);
        float inv = 1.f / ssum;
        float a0 = e0 * inv, a1 = e1 * inv;
        Ad4[(pbase + p) * AD_STRIDE + ni] = make_float4(a0, a0, a1, a1);
    }
    __syncthreads();   // cs region is dead from here on -> reused as merge buffer

    // ---- Phase D (split): warp (h = w>>2, v = w&3): points [32h,32h+32), k-octet 8v..8v+7.
    //      Per point: 1 distinct LDS.128 (x) + 4 broadcast pair loads (A) + 16 FFMA2. ----
    const int v = w & 3;
    const int h = w >> 2;
    unsigned long long acc2[16];
    #pragma unroll
    for (int q = 0; q < 16; ++q) acc2[q] = 0ull;
    const ulonglong2* Ad2 = (const ulonglong2*)Ad4;
    const int p0 = 32 * h;

    #pragma unroll 8
    for (int i = 0; i < 32; ++i) {
        int p = p0 + i;
        ulonglong2 xv = xs2[p * XS_STRIDE + lane];           // distinct, conflict-free
        ulonglong2 a0 = Ad2[p * AD_STRIDE + 4 * v + 0];      // (a,a) pairs, broadcast
        ulonglong2 a1 = Ad2[p * AD_STRIDE + 4 * v + 1];
        ulonglong2 a2 = Ad2[p * AD_STRIDE + 4 * v + 2];
        ulonglong2 a3 = Ad2[p * AD_STRIDE + 4 * v + 3];
        acc2[ 0] = ffma2_(a0.x, xv.x, acc2[ 0]);
        acc2[ 1] = ffma2_(a0.x, xv.y, acc2[ 1]);
        acc2[ 2] = ffma2_(a0.y, xv.x, acc2[ 2]);
        acc2[ 3] = ffma2_(a0.y, xv.y, acc2[ 3]);
        acc2[ 4] = ffma2_(a1.x, xv.x, acc2[ 4]);
        acc2[ 5] = ffma2_(a1.x, xv.y, acc2[ 5]);
        acc2[ 6] = ffma2_(a1.y, xv.x, acc2[ 6]);
        acc2[ 7] = ffma2_(a1.y, xv.y, acc2[ 7]);
        acc2[ 8] = ffma2_(a2.x, xv.x, acc2[ 8]);
        acc2[ 9] = ffma2_(a2.x, xv.y, acc2[ 9]);
        acc2[10] = ffma2_(a2.y, xv.x, acc2[10]);
        acc2[11] = ffma2_(a2.y, xv.y, acc2[11]);
        acc2[12] = ffma2_(a3.x, xv.x, acc2[12]);
        acc2[13] = ffma2_(a3.x, xv.y, acc2[13]);
        acc2[14] = ffma2_(a3.y, xv.x, acc2[14]);
        acc2[15] = ffma2_(a3.y, xv.y, acc2[15]);
    }

    if (h == 1) {
        // store partials for merge (cs region), then compute sA for this k-octet
        #pragma unroll
        for (int jj = 0; jj < 8; ++jj) {
            ulonglong2 tv; tv.x = acc2[2 * jj]; tv.y = acc2[2 * jj + 1];
            buf2[(v * 8 + jj) * 32 + lane] = tv;             // conflict-free STS.128
        }
        // sA_kk = sum over ALL 64 points of A[p][8v+kk]
        float sa[8] = {0.f, 0.f, 0.f, 0.f, 0.f, 0.f, 0.f, 0.f};
        #pragma unroll
        for (int hh = 0; hh < 2; ++hh) {
            int p = lane + 32 * hh;
            #pragma unroll
            for (int j = 0; j < 4; ++j) {
                float4 u = Ad4[p * AD_STRIDE + 4 * v + j];   // (a2j,a2j,a2j+1,a2j+1)
                sa[2 * j]     += u.x;
                sa[2 * j + 1] += u.z;
            }
        }
        #pragma unroll
        for (int o = 16; o; o >>= 1) {
            #pragma unroll
            for (int q = 0; q < 8; ++q)
                sa[q] += __shfl_xor_sync(0xffffffffu, sa[q], o);
        }
        if (lane == 0) {
            ((float4*)sabf)[2 * v + 0] = make_float4(sa[0], sa[1], sa[2], sa[3]);
            ((float4*)sabf)[2 * v + 1] = make_float4(sa[4], sa[5], sa[6], sa[7]);
        }
    }
    __syncthreads();

    if (h == 0) {
        // merge the other half's partials
        #pragma unroll
        for (int jj = 0; jj < 8; ++jj) {
            ulonglong2 tv = buf2[(v * 8 + jj) * 32 + lane];
            acc2[2 * jj]     = add2_(acc2[2 * jj],     tv.x);
            acc2[2 * jj + 1] = add2_(acc2[2 * jj + 1], tv.y);
        }
        // epilogue: out[b][8v+kk][4*lane..+3] += acc - sA*c   (red.v4)
        #pragma unroll
        for (int kk = 0; kk < 8; ++kk) {
            int k = 8 * v + kk;
            int j = kk >> 1, which = kk & 1;
            float sj = sabf[v * 8 + kk];                     // broadcast LDS
            float4 c = ((const float4*)cw)[k * 32 + lane];   // coalesced LDG.128
            float2 lo = unpack2(acc2[4 * j + 2 * which + 0]);
            float2 hi = unpack2(acc2[4 * j + 2 * which + 1]);
            red_add_v4(out + ((size_t)b * KK + k) * DD + 4 * lane,
                       fmaf(-sj, c.x, lo.x),
                       fmaf(-sj, c.y, lo.y),
                       fmaf(-sj, c.z, hi.x),
                       fmaf(-sj, c.w, hi.y));
        }
    }
}

extern "C" void kernel_launch(void* const* d_in, const int* in_sizes, int n_in,
                              void* d_out, int out_size) {
    const float* x  = (const float*)d_in[0];   // [16,32,32,128]
    const float* cw = (const float*)d_in[1];   // [32,128]
    const float* sc = (const float*)d_in[2];   // [32]
    float* out = (float*)d_out;                // [16,32,128]

    cudaFuncSetAttribute(ev_encode_kernel,
                         cudaFuncAttributeMaxDynamicSharedMemorySize, SMEM_BYTES);

    // out is poisoned by the harness; REDs need zeros
    ev_zero_kernel<<<(BB * KK * DD / 4) / 256, 256>>>((float4*)out);
    ev_encode_kernel<<<NCHUNK, NTHREADS, SMEM_BYTES>>>(x, cw, sc, out);
}

// round 14
// speedup vs baseline: 1.2448x; 1.0323x over previous
#include <cuda_runtime.h>

// Shapes fixed by reference setup_inputs()
#define BB      16
#define NPTS    1024          // H*W
#define DD      128           // = 32 float4 chunks
#define KK      32
#define GPB     16            // chunks (CTAs) per batch
#define PPB     (NPTS / GPB)  // 64 points per CTA
#define NTHREADS 256
#define NCHUNK  (BB * GPB)    // 256

// Shared layout: xs[64][33] f4 | cs[32][34] f4 (later reused as merge buf) |
//                Ad[64][17] f4 (dup pairs) | x2s[64] f
#define XS_STRIDE 33
#define CS_STRIDE 34
#define AD_STRIDE 17
#define XS_BYTES  (PPB * XS_STRIDE * 16)            // 33792
#define CS_BYTES  (KK * CS_STRIDE * 16)             // 17408
#define AD_BYTES  (PPB * AD_STRIDE * 16)            // 17408
#define SMEM_BYTES (XS_BYTES + CS_BYTES + AD_BYTES + PPB * 4)  // 68864

__device__ __forceinline__ unsigned long long ffma2_(unsigned long long a,
                                                     unsigned long long b,
                                                     unsigned long long c) {
    unsigned long long d;
    asm("fma.rn.f32x2 %0, %1, %2, %3;" : "=l"(d) : "l"(a), "l"(b), "l"(c));
    return d;
}
__device__ __forceinline__ unsigned long long add2_(unsigned long long a,
                                                    unsigned long long b) {
    unsigned long long d;
    asm("add.rn.f32x2 %0, %1, %2;" : "=l"(d) : "l"(a), "l"(b));
    return d;
}
__device__ __forceinline__ float2 unpack2(unsigned long long v) {
    float2 r;
    asm("mov.b64 {%0, %1}, %2;" : "=f"(r.x), "=f"(r.y) : "l"(v));
    return r;
}
// Vector reduction: fire-and-forget float4 add to global (sm_90+)
__device__ __forceinline__ void red_add_v4(float* p, float a, float b, float c, float d) {
    asm volatile("red.global.add.v4.f32 [%0], {%1, %2, %3, %4};"
                 :: "l"(p), "f"(a), "f"(b), "f"(c), "f"(d) : "memory");
}

__global__ __launch_bounds__(NTHREADS, 2)
void ev_encode_kernel(const float* __restrict__ x,
                      const float* __restrict__ cw,
                      const float* __restrict__ scale,
                      float* __restrict__ out) {
    extern __shared__ char sraw[];
    float4* xs  = (float4*)sraw;                          // [PPB][33]
    float4* cs  = (float4*)(sraw + XS_BYTES);             // [KK][34] rotated
    float4* Ad4 = (float4*)(sraw + XS_BYTES + CS_BYTES);  // [PPB][17]: (a,a) dup pairs
    float*  x2s = (float*)(sraw + XS_BYTES + CS_BYTES + AD_BYTES);  // [PPB]
    // Phase-D merge buffers reuse the cs region (dead after softmax):
    ulonglong2* buf2 = (ulonglong2*)cs;                   // [4v][8jj][32 lane] 16B = 16KB
    float*      sabf = (float*)(sraw + XS_BYTES + 16384); // [4v][8kk] floats (128B)

    const int t    = threadIdx.x;
    const int lane = t & 31;
    const int w    = t >> 5;              // 0..7
    const int b    = blockIdx.x >> 4;
    const int g    = blockIdx.x & 15;
    const int mi   = lane & 1;            // point-subgroup (2 x 4 pts)
    const int ni   = lane >> 1;           // k-pair index (16 pairs)

    // ---- Phase A1: stage x tile; warp w loads complete rows w, w+8, ...
    const float4* xg = (const float4*)(x + ((size_t)b * NPTS + (size_t)g * PPB) * DD);
    #pragma unroll
    for (int i = 0; i < 8; ++i) {
        int p = w + 8 * i;
        float4 v = xg[p * 32 + lane];
        xs[p * XS_STRIDE + lane] = v;
        float s2 = v.x * v.x + v.y * v.y + v.z * v.z + v.w * v.w;
        #pragma unroll
        for (int o = 16; o; o >>= 1) s2 += __shfl_xor_sync(0xffffffffu, s2, o);
        if (lane == 0) x2s[p] = s2;
    }

    // ---- Phase A2: augmented codewords w_k = -2*s_k*c_k at slot (d4 + k/2)&31;
    //      slot 32 = (s_k, s_k*||c_k||^2, 0, 0). Warp w builds rows 4w..4w+3. ----
    #pragma unroll
    for (int j = 0; j < 4; ++j) {
        int k = w * 4 + j;
        float4 c = ((const float4*)cw)[k * 32 + lane];
        float s  = scale[k];
        float c2 = c.x * c.x + c.y * c.y + c.z * c.z + c.w * c.w;
        #pragma unroll
        for (int o = 16; o; o >>= 1) c2 += __shfl_xor_sync(0xffffffffu, c2, o);
        float m2 = -2.f * s;
        cs[k * CS_STRIDE + ((lane + (k >> 1)) & 31)] =
            make_float4(m2 * c.x, m2 * c.y, m2 * c.z, m2 * c.w);
        if (lane == 0)
            cs[k * CS_STRIDE + 32] = make_float4(s, s * c2, 0.f, 0.f);
    }
    __syncthreads();

    // ---- Phase C: stage-1 GEMM (logits), 4 pts x 2 k per lane; FULL unroll ----
    unsigned long long acc[4][2];
    #pragma unroll
    for (int p = 0; p < 4; ++p) { acc[p][0] = 0ull; acc[p][1] = 0ull; }

    const int pbase = w * 8 + mi * 4;
    const ulonglong2* xs2 = (const ulonglong2*)xs;
    const ulonglong2* csrow0 = (const ulonglong2*)cs + (2 * ni + 0) * CS_STRIDE;
    const ulonglong2* csrow1 = (const ulonglong2*)cs + (2 * ni + 1) * CS_STRIDE;

    #pragma unroll
    for (int d4 = 0; d4 < 32; ++d4) {
        int cslot = (d4 + ni) & 31;
        ulonglong2 cv0 = csrow0[cslot];
        ulonglong2 cv1 = csrow1[cslot];
        #pragma unroll
        for (int p = 0; p < 4; ++p) {
            ulonglong2 xv = xs2[(pbase + p) * XS_STRIDE + d4];
            acc[p][0] = ffma2_(cv0.x, xv.x, acc[p][0]);
            acc[p][0] = ffma2_(cv0.y, xv.y, acc[p][0]);
            acc[p][1] = ffma2_(cv1.x, xv.x, acc[p][1]);
            acc[p][1] = ffma2_(cv1.y, xv.y, acc[p][1]);
        }
    }

    float4 cc0 = cs[(2 * ni + 0) * CS_STRIDE + 32];   // (s, s*c2, 0, 0)
    float4 cc1 = cs[(2 * ni + 1) * CS_STRIDE + 32];

    // ---- softmax over K=32; store A pre-duplicated pairs ----
    #pragma unroll
    for (int p = 0; p < 4; ++p) {
        float x2 = x2s[pbase + p];
        float2 u0 = unpack2(acc[p][0]);
        float2 u1 = unpack2(acc[p][1]);
        float SL0 = (u0.x + u0.y) + fmaf(cc0.x, x2, cc0.y);
        float SL1 = (u1.x + u1.y) + fmaf(cc1.x, x2, cc1.y);
        float m = fmaxf(SL0, SL1);
        #pragma unroll
        for (int o = 2; o <= 16; o <<= 1) m = fmaxf(m, __shfl_xor_sync(0xffffffffu, m, o));
        float e0 = __expf(SL0 - m);
        float e1 = __expf(SL1 - m);
        float ssum = e0 + e1;
        #pragma unroll
        for (int o = 2; o <= 16; o <<= 1) ssum += __shfl_xor_sync(0xffffffffu, ssum, o);
        float inv = 1.f / ssum;
        float a0 = e0 * inv, a1 = e1 * inv;
        Ad4[(pbase + p) * AD_STRIDE + ni] = make_float4(a0, a0, a1, a1);
    }
    __syncthreads();   // cs region is dead from here on -> reused as merge buffer

    // ---- Phase D (split): warp (h = w>>2, v = w&3): points [32h,32h+32), k-octet 8v..8v+7.
    //      Per point: 1 distinct LDS.128 (x) + 4 broadcast pair loads (A) + 16 FFMA2. ----
    const int v = w & 3;
    const int h = w >> 2;
    unsigned long long acc2[16];
    #pragma unroll
    for (int q = 0; q < 16; ++q) acc2[q] = 0ull;
    const ulonglong2* Ad2 = (const ulonglong2*)Ad4;
    const int p0 = 32 * h;

    #pragma unroll 16
    for (int i = 0; i < 32; ++i) {
        int p = p0 + i;
        ulonglong2 xv = xs2[p * XS_STRIDE + lane];           // distinct, conflict-free
        ulonglong2 a0 = Ad2[p * AD_STRIDE + 4 * v + 0];      // (a,a) pairs, broadcast
        ulonglong2 a1 = Ad2[p * AD_STRIDE + 4 * v + 1];
        ulonglong2 a2 = Ad2[p * AD_STRIDE + 4 * v + 2];
        ulonglong2 a3 = Ad2[p * AD_STRIDE + 4 * v + 3];
        acc2[ 0] = ffma2_(a0.x, xv.x, acc2[ 0]);
        acc2[ 1] = ffma2_(a0.x, xv.y, acc2[ 1]);
        acc2[ 2] = ffma2_(a0.y, xv.x, acc2[ 2]);
        acc2[ 3] = ffma2_(a0.y, xv.y, acc2[ 3]);
        acc2[ 4] = ffma2_(a1.x, xv.x, acc2[ 4]);
        acc2[ 5] = ffma2_(a1.x, xv.y, acc2[ 5]);
        acc2[ 6] = ffma2_(a1.y, xv.x, acc2[ 6]);
        acc2[ 7] = ffma2_(a1.y, xv.y, acc2[ 7]);
        acc2[ 8] = ffma2_(a2.x, xv.x, acc2[ 8]);
        acc2[ 9] = ffma2_(a2.x, xv.y, acc2[ 9]);
        acc2[10] = ffma2_(a2.y, xv.x, acc2[10]);
        acc2[11] = ffma2_(a2.y, xv.y, acc2[11]);
        acc2[12] = ffma2_(a3.x, xv.x, acc2[12]);
        acc2[13] = ffma2_(a3.x, xv.y, acc2[13]);
        acc2[14] = ffma2_(a3.y, xv.x, acc2[14]);
        acc2[15] = ffma2_(a3.y, xv.y, acc2[15]);
    }

    if (h == 1) {
        // store partials for merge (cs region), then compute sA for this k-octet
        #pragma unroll
        for (int jj = 0; jj < 8; ++jj) {
            ulonglong2 tv; tv.x = acc2[2 * jj]; tv.y = acc2[2 * jj + 1];
            buf2[(v * 8 + jj) * 32 + lane] = tv;             // conflict-free STS.128
        }
        // sA_kk = sum over ALL 64 points of A[p][8v+kk]
        float sa[8] = {0.f, 0.f, 0.f, 0.f, 0.f, 0.f, 0.f, 0.f};
        #pragma unroll
        for (int hh = 0; hh < 2; ++hh) {
            int p = lane + 32 * hh;
            #pragma unroll
            for (int j = 0; j < 4; ++j) {
                float4 u = Ad4[p * AD_STRIDE + 4 * v + j];   // (a2j,a2j,a2j+1,a2j+1)
                sa[2 * j]     += u.x;
                sa[2 * j + 1] += u.z;
            }
        }
        #pragma unroll
        for (int o = 16; o; o >>= 1) {
            #pragma unroll
            for (int q = 0; q < 8; ++q)
                sa[q] += __shfl_xor_sync(0xffffffffu, sa[q], o);
        }
        if (lane == 0) {
            ((float4*)sabf)[2 * v + 0] = make_float4(sa[0], sa[1], sa[2], sa[3]);
            ((float4*)sabf)[2 * v + 1] = make_float4(sa[4], sa[5], sa[6], sa[7]);
        }
    }
    __syncthreads();

    if (h == 0) {
        // merge the other half's partials
        #pragma unroll
        for (int jj = 0; jj < 8; ++jj) {
            ulonglong2 tv = buf2[(v * 8 + jj) * 32 + lane];
            acc2[2 * jj]     = add2_(acc2[2 * jj],     tv.x);
            acc2[2 * jj + 1] = add2_(acc2[2 * jj + 1], tv.y);
        }
        // epilogue: out[b][8v+kk][4*lane..+3] += acc - sA*c   (red.v4)
        #pragma unroll
        for (int kk = 0; kk < 8; ++kk) {
            int k = 8 * v + kk;
            int j = kk >> 1, which = kk & 1;
            float sj = sabf[v * 8 + kk];                     // broadcast LDS
            float4 c = ((const float4*)cw)[k * 32 + lane];   // coalesced LDG.128
            float2 lo = unpack2(acc2[4 * j + 2 * which + 0]);
            float2 hi = unpack2(acc2[4 * j + 2 * which + 1]);
            red_add_v4(out + ((size_t)b * KK + k) * DD + 4 * lane,
                       fmaf(-sj, c.x, lo.x),
                       fmaf(-sj, c.y, lo.y),
                       fmaf(-sj, c.z, hi.x),
                       fmaf(-sj, c.w, hi.y));
        }
    }
}

extern "C" void kernel_launch(void* const* d_in, const int* in_sizes, int n_in,
                              void* d_out, int out_size) {
    const float* x  = (const float*)d_in[0];   // [16,32,32,128]
    const float* cw = (const float*)d_in[1];   // [32,128]
    const float* sc = (const float*)d_in[2];   // [32]
    float* out = (float*)d_out;                // [16,32,128]

    cudaFuncSetAttribute(ev_encode_kernel,
                         cudaFuncAttributeMaxDynamicSharedMemorySize, SMEM_BYTES);

    // out is poisoned by the harness; REDs need zeros. Memset node, no kernel launch.
    cudaMemsetAsync(out, 0, (size_t)out_size * sizeof(float));
    ev_encode_kernel<<<NCHUNK, NTHREADS, SMEM_BYTES>>>(x, cw, sc, out);
}